// round 2
// baseline (speedup 1.0000x reference)
#include <cuda_runtime.h>

#define B_TOT 4096
#define B_HALF 2048
#define PAD 130

// ---------------- device scratch (no allocations allowed) ----------------
__device__ float g_zt[B_TOT * 64];      // ReLU(linear) features
__device__ float g_s[B_TOT];            // attention scores
__device__ float g_e[B_TOT];            // exp(s - m) per group
__device__ float g_T[2];                // sum of e per group
__device__ float g_Z[128];              // [2][64] sum e*zt per group
__device__ float g_pred[B_TOT * 128];   // prediction matrix
__device__ float g_diag[B_TOT];         // total[i,i]
__device__ float g_pM[32 * B_TOT];      // per-colblock row max
__device__ float g_pS[32 * B_TOT];      // per-colblock row sumexp
__device__ float g_rowvals[B_TOT];      // lse_i - diag_i

__device__ __forceinline__ void ffma2(unsigned long long& d,
                                      unsigned long long a,
                                      unsigned long long b) {
    asm("fma.rn.f32x2 %0, %1, %2, %0;" : "+l"(d) : "l"(a), "l"(b));
}

// ---------------- K1: zt = relu(zw @ lw.T + lb); s = tanh(zt@a1.T+b)@a2.T+b2
__global__ void __launch_bounds__(128) k_zt_s(
    const float* __restrict__ zw0, const float* __restrict__ zw1,
    const float* __restrict__ l0w, const float* __restrict__ l0b,
    const float* __restrict__ l1w, const float* __restrict__ l1b,
    const float* __restrict__ a01w, const float* __restrict__ a01b,
    const float* __restrict__ a02w, const float* __restrict__ a02b,
    const float* __restrict__ a11w, const float* __restrict__ a11b,
    const float* __restrict__ a12w, const float* __restrict__ a12b)
{
    __shared__ float lw_s[64 * 132];
    __shared__ float awT[64 * 32];
    __shared__ float lb_s[64], ab_s[32], a2_s[32];
    __shared__ float zw_s[2][128];
    __shared__ float zt_s[2][64];
    __shared__ float a2b_s;
    int tid = threadIdx.x;
    int row0 = blockIdx.x * 32;
    int g = (row0 >= B_HALF);
    const float* zw  = g ? (zw1 + (row0 - B_HALF) * 128) : (zw0 + row0 * 128);
    const float* lw  = g ? l1w : l0w;
    const float* lb  = g ? l1b : l0b;
    const float* a1w = g ? a11w : a01w;
    const float* a1b = g ? a11b : a01b;
    const float* a2w = g ? a12w : a02w;
    const float* a2b = g ? a12b : a02b;

    for (int n = tid; n < 2048; n += 128) {      // 64x128 floats as float4
        float4 v = ((const float4*)lw)[n];
        int t = n >> 5; int k4 = (n & 31) * 4;
        *((float4*)&lw_s[t * 132 + k4]) = v;
    }
    for (int n = tid; n < 512; n += 128) {       // 32x64 floats as float4
        float4 v = ((const float4*)a1w)[n];
        int t = n >> 4; int k = (n & 15) * 4;
        awT[(k + 0) * 32 + t] = v.x; awT[(k + 1) * 32 + t] = v.y;
        awT[(k + 2) * 32 + t] = v.z; awT[(k + 3) * 32 + t] = v.w;
    }
    if (tid < 64) lb_s[tid] = lb[tid];
    if (tid < 32) { ab_s[tid] = a1b[tid]; a2_s[tid] = a2w[tid]; }
    if (tid == 0) a2b_s = a2b[0];
    __syncthreads();

    for (int rp = 0; rp < 32; rp += 2) {
        ((float*)zw_s)[tid]       = zw[rp * 128 + tid];
        ((float*)zw_s)[tid + 128] = zw[rp * 128 + tid + 128];
        __syncthreads();
        int t = tid & 63, rs = tid >> 6;
        float acc = lb_s[t];
        #pragma unroll
        for (int k = 0; k < 128; k += 4) {
            float4 w = *((const float4*)&lw_s[t * 132 + k]);
            float4 z = *((const float4*)&zw_s[rs][k]);
            acc += w.x * z.x + w.y * z.y + w.z * z.z + w.w * z.w;
        }
        float zt = fmaxf(acc, 0.0f);
        zt_s[rs][t] = zt;
        g_zt[(row0 + rp + rs) * 64 + t] = zt;
        __syncthreads();
        if (tid < 64) {
            int r = tid >> 5, j = tid & 31;
            float h = ab_s[j];
            #pragma unroll
            for (int k = 0; k < 64; k++) h += zt_s[r][k] * awT[k * 32 + j];
            h = tanhf(h);
            float v = h * a2_s[j];
            #pragma unroll
            for (int o = 16; o; o >>= 1) v += __shfl_xor_sync(0xffffffffu, v, o);
            if (j == 0) g_s[row0 + rp + r] = v + a2b_s;
        }
        __syncthreads();
    }
}

// ---------------- K2: per-group m, e, T, Z ----------------
__global__ void __launch_bounds__(1024) k_stats() {
    __shared__ float red[1024];
    int g = blockIdx.x;
    int base = g * B_HALF;
    int tid = threadIdx.x;
    float m = fmaxf(g_s[base + tid], g_s[base + tid + 1024]);
    red[tid] = m; __syncthreads();
    for (int s = 512; s > 0; s >>= 1) {
        if (tid < s) red[tid] = fmaxf(red[tid], red[tid + s]);
        __syncthreads();
    }
    m = red[0];
    __syncthreads();
    float e0 = __expf(g_s[base + tid] - m);
    float e1 = __expf(g_s[base + tid + 1024] - m);
    g_e[base + tid] = e0; g_e[base + tid + 1024] = e1;
    red[tid] = e0 + e1; __syncthreads();
    for (int s = 512; s > 0; s >>= 1) {
        if (tid < s) red[tid] += red[tid + s];
        __syncthreads();
    }
    if (tid == 0) g_T[g] = red[0];
    // Z[d] = sum_r e_r * zt[r][d]   (64 dims x 16 partial threads)
    int d = tid >> 4, sub = tid & 15;
    float z = 0.f;
    for (int r = sub; r < B_HALF; r += 16)
        z += g_e[base + r] * g_zt[(base + r) * 64 + d];
    #pragma unroll
    for (int o = 8; o; o >>= 1) z += __shfl_xor_sync(0xffffffffu, z, o);
    if (sub == 0) g_Z[g * 64 + d] = z;
}

// ---------------- K3: pred[row] = pooled@Ww.T + Wwb + c@Wk.T + Wkb --------
__global__ void __launch_bounds__(128) k_pred(
    const float* __restrict__ c,
    const float* __restrict__ Wkw, const float* __restrict__ Wkb,
    const float* __restrict__ Ww0w, const float* __restrict__ Ww0b,
    const float* __restrict__ Ww1w, const float* __restrict__ Ww1b)
{
    extern __shared__ float sm3[];
    float* W_s = sm3;                 // [128 j][132]  (k<64: Ww, k>=64: Wk)
    float* u_s = sm3 + 128 * 132;     // [128]
    float* b_s = u_s + 128;           // [128]
    int tid = threadIdx.x;
    int row0 = blockIdx.x * 32;
    int g = (row0 >= B_HALF);
    const float* Ww = g ? Ww1w : Ww0w;
    const float* Wb = g ? Ww1b : Ww0b;
    for (int n = tid; n < 4096; n += 128) {
        int j = n >> 5, q = n & 31;
        float4 v; int off;
        if (q < 16) { v = ((const float4*)Ww)[j * 16 + q];        off = q * 4; }
        else        { v = ((const float4*)Wkw)[j * 16 + (q - 16)]; off = 64 + (q - 16) * 4; }
        *((float4*)&W_s[j * 132 + off]) = v;
    }
    b_s[tid] = Wb[tid] + Wkb[tid];
    __syncthreads();
    float Tg = g_T[g];
    for (int r = 0; r < 32; r++) {
        int row = row0 + r;
        if (tid < 64) {
            float e  = g_e[row];
            float zt = g_zt[row * 64 + tid];
            u_s[tid] = (g_Z[g * 64 + tid] - e * zt) / (Tg - e);
        } else {
            u_s[tid] = c[row * 64 + (tid - 64)];
        }
        __syncthreads();
        float acc = b_s[tid];
        #pragma unroll
        for (int k = 0; k < 128; k += 4) {
            float4 w = *((const float4*)&W_s[tid * 132 + k]);
            float4 u = *((const float4*)&u_s[k]);
            acc += w.x * u.x + w.y * u.y + w.z * u.z + w.w * u.w;
        }
        g_pred[row * 128 + tid] = acc;
        __syncthreads();
    }
}

// ---------------- K4: fused zw @ pred.T + per-row (max, sumexp, diag) -----
// grid (32 colblocks, 32 rowblocks), 128x128 tile, 8x8 frags, f32x2 FMA.
__global__ void __launch_bounds__(256) k_gemm_lse(
    const float* __restrict__ zw0, const float* __restrict__ zw1)
{
    extern __shared__ float sm4[];
    float* As = sm4;
    float* Bs = sm4 + 128 * PAD;
    int cb = blockIdx.x, rb = blockIdx.y;
    int tid = threadIdx.x;
    int row0 = rb * 128;
    const float* abase = (row0 < B_HALF) ? (zw0 + row0 * 128)
                                         : (zw1 + (row0 - B_HALF) * 128);
    const float* bbase = g_pred + cb * 128 * 128;
    for (int n = tid; n < 4096; n += 256) {
        int r = n >> 5, c4 = (n & 31) * 4;
        float4 v = ((const float4*)abase)[n];
        float2* d = (float2*)&As[r * PAD + c4];
        d[0] = make_float2(v.x, v.y); d[1] = make_float2(v.z, v.w);
        float4 w = ((const float4*)bbase)[n];
        float2* d2 = (float2*)&Bs[r * PAD + c4];
        d2[0] = make_float2(w.x, w.y); d2[1] = make_float2(w.z, w.w);
    }
    __syncthreads();
    int tx = tid & 15, ty = tid >> 4;   // strided frags: rows ty+16i, cols tx+16j
    unsigned long long acc2[8][8];
    #pragma unroll
    for (int i = 0; i < 8; i++)
        #pragma unroll
        for (int j = 0; j < 8; j++) acc2[i][j] = 0ull;
    const float* arow = As + ty * PAD;
    const float* brow = Bs + tx * PAD;
    #pragma unroll 2
    for (int k = 0; k < 128; k += 2) {
        unsigned long long a[8], b[8];
        #pragma unroll
        for (int i = 0; i < 8; i++)
            a[i] = *((const unsigned long long*)&arow[i * 16 * PAD + k]);
        #pragma unroll
        for (int j = 0; j < 8; j++)
            b[j] = *((const unsigned long long*)&brow[j * 16 * PAD + k]);
        #pragma unroll
        for (int i = 0; i < 8; i++)
            #pragma unroll
            for (int j = 0; j < 8; j++)
                ffma2(acc2[i][j], a[i], b[j]);
    }
    // epilogue: per-row max + sumexp across the 16 tx lanes, capture diag
    #pragma unroll
    for (int i = 0; i < 8; i++) {
        float v[8];
        float lm = -1e30f;
        #pragma unroll
        for (int j = 0; j < 8; j++) {
            unsigned long long u = acc2[i][j];
            float lo = __uint_as_float((unsigned)u);
            float hi = __uint_as_float((unsigned)(u >> 32));
            v[j] = lo + hi;
            lm = fmaxf(lm, v[j]);
        }
        #pragma unroll
        for (int o = 8; o; o >>= 1)
            lm = fmaxf(lm, __shfl_xor_sync(0xffffffffu, lm, o));
        float se = 0.f;
        #pragma unroll
        for (int j = 0; j < 8; j++) se += __expf(v[j] - lm);
        #pragma unroll
        for (int o = 8; o; o >>= 1) se += __shfl_xor_sync(0xffffffffu, se, o);
        int grow = row0 + ty + 16 * i;
        if (rb == cb && tx == ty) g_diag[grow] = v[i];
        if (tx == 0) { g_pM[cb * B_TOT + grow] = lm; g_pS[cb * B_TOT + grow] = se; }
    }
}

// ---------------- K5: combine 32 partials per row -> lse - diag ----------
__global__ void __launch_bounds__(128) k_combine() {
    int i = blockIdx.x * 128 + threadIdx.x;
    float M = -1e30f;
    #pragma unroll
    for (int p = 0; p < 32; p++) M = fmaxf(M, g_pM[p * B_TOT + i]);
    float S = 0.f;
    #pragma unroll
    for (int p = 0; p < 32; p++)
        S += g_pS[p * B_TOT + i] * __expf(g_pM[p * B_TOT + i] - M);
    g_rowvals[i] = M + logf(S) - g_diag[i];
}

// ---------------- K6: deterministic final reduction ----------------------
__global__ void __launch_bounds__(1024) k_final(float* __restrict__ out) {
    __shared__ double red[1024];
    int tid = threadIdx.x;
    double v = (double)g_rowvals[tid] + (double)g_rowvals[tid + 1024]
             + (double)g_rowvals[tid + 2048] + (double)g_rowvals[tid + 3072];
    red[tid] = v; __syncthreads();
    for (int s = 512; s > 0; s >>= 1) {
        if (tid < s) red[tid] += red[tid + s];
        __syncthreads();
    }
    if (tid == 0) out[0] = (float)(red[0] / 4096.0);
}

extern "C" void kernel_launch(void* const* d_in, const int* in_sizes, int n_in,
                              void* d_out, int out_size) {
    const float* zw0  = (const float*)d_in[0];
    const float* zw1  = (const float*)d_in[1];
    const float* c    = (const float*)d_in[2];
    const float* Wkw  = (const float*)d_in[3];
    const float* Wkb  = (const float*)d_in[4];
    const float* Ww0w = (const float*)d_in[5];
    const float* Ww0b = (const float*)d_in[6];
    const float* Ww1w = (const float*)d_in[7];
    const float* Ww1b = (const float*)d_in[8];
    const float* l0w  = (const float*)d_in[9];
    const float* l0b  = (const float*)d_in[10];
    const float* l1w  = (const float*)d_in[11];
    const float* l1b  = (const float*)d_in[12];
    const float* a01w = (const float*)d_in[13];
    const float* a01b = (const float*)d_in[14];
    const float* a02w = (const float*)d_in[15];
    const float* a02b = (const float*)d_in[16];
    const float* a11w = (const float*)d_in[17];
    const float* a11b = (const float*)d_in[18];
    const float* a12w = (const float*)d_in[19];
    const float* a12b = (const float*)d_in[20];
    float* out = (float*)d_out;

    cudaFuncSetAttribute(k_pred, cudaFuncAttributeMaxDynamicSharedMemorySize,
                         (128 * 132 + 256) * 4);
    cudaFuncSetAttribute(k_gemm_lse, cudaFuncAttributeMaxDynamicSharedMemorySize,
                         2 * 128 * PAD * 4);

    k_zt_s<<<128, 128>>>(zw0, zw1, l0w, l0b, l1w, l1b,
                         a01w, a01b, a02w, a02b, a11w, a11b, a12w, a12b);
    k_stats<<<2, 1024>>>();
    k_pred<<<128, 128, (128 * 132 + 256) * 4>>>(c, Wkw, Wkb, Ww0w, Ww0b, Ww1w, Ww1b);
    k_gemm_lse<<<dim3(32, 32), 256, 2 * 128 * PAD * 4>>>(zw0, zw1);
    k_combine<<<32, 128>>>();
    k_final<<<1, 1024>>>(out);
}

// round 6
// speedup vs baseline: 1.8542x; 1.8542x over previous
#include <cuda_runtime.h>
#include <cuda_bf16.h>
#include <cstdint>

#define B_TOT 4096
#define B_HALF 2048

// ---------------- device scratch ----------------
__device__ float g_zt[B_TOT * 64];
__device__ float g_s[B_TOT];
__device__ float g_e[B_TOT];
__device__ float g_T[2];
__device__ float g_Zp[32 * 64];
__device__ __align__(16) float g_pred[B_TOT * 128];
__device__ float g_diag[B_TOT];
__device__ float g_pM[32 * B_TOT];
__device__ float g_pS[32 * B_TOT];
__device__ float g_rowvals[B_TOT];
__device__ __align__(16) unsigned short g_A[B_TOT * 384];  // bf16 [hi|lo|hi]
__device__ __align__(16) unsigned short g_B[B_TOT * 384];  // bf16 [hi|hi|lo]

__device__ __forceinline__ uint32_t smem_u32(const void* p) {
    uint32_t a;
    asm("{ .reg .u64 t; cvta.to.shared.u64 t, %1; cvt.u32.u64 %0, t; }"
        : "=r"(a) : "l"(p));
    return a;
}

// ---------------- K1: zt = relu(zw @ lw.T + lb); attention score s --------
__global__ void __launch_bounds__(128) k_zt_s(
    const float* __restrict__ zw0, const float* __restrict__ zw1,
    const float* __restrict__ l0w, const float* __restrict__ l0b,
    const float* __restrict__ l1w, const float* __restrict__ l1b,
    const float* __restrict__ a01w, const float* __restrict__ a01b,
    const float* __restrict__ a02w, const float* __restrict__ a02b,
    const float* __restrict__ a11w, const float* __restrict__ a11b,
    const float* __restrict__ a12w, const float* __restrict__ a12b)
{
    __shared__ float lw_s[64 * 132];
    __shared__ float awT[64 * 32];
    __shared__ float lb_s[64], ab_s[32], a2_s[32];
    __shared__ float zw_s[2][128];
    __shared__ float zt_s[2][64];
    __shared__ float a2b_s;
    int tid = threadIdx.x;
    int row0 = blockIdx.x * 32;
    int g = (row0 >= B_HALF);
    const float* zw  = g ? (zw1 + (row0 - B_HALF) * 128) : (zw0 + row0 * 128);
    const float* lw  = g ? l1w : l0w;
    const float* lb  = g ? l1b : l0b;
    const float* a1w = g ? a11w : a01w;
    const float* a1b = g ? a11b : a01b;
    const float* a2w = g ? a12w : a02w;
    const float* a2b = g ? a12b : a02b;

    for (int n = tid; n < 2048; n += 128) {
        float4 v = ((const float4*)lw)[n];
        int t = n >> 5; int k4 = (n & 31) * 4;
        *((float4*)&lw_s[t * 132 + k4]) = v;
    }
    for (int n = tid; n < 512; n += 128) {
        float4 v = ((const float4*)a1w)[n];
        int t = n >> 4; int k = (n & 15) * 4;
        awT[(k + 0) * 32 + t] = v.x; awT[(k + 1) * 32 + t] = v.y;
        awT[(k + 2) * 32 + t] = v.z; awT[(k + 3) * 32 + t] = v.w;
    }
    if (tid < 64) lb_s[tid] = lb[tid];
    if (tid < 32) { ab_s[tid] = a1b[tid]; a2_s[tid] = a2w[tid]; }
    if (tid == 0) a2b_s = a2b[0];
    __syncthreads();

    for (int rp = 0; rp < 32; rp += 2) {
        ((float*)zw_s)[tid]       = zw[rp * 128 + tid];
        ((float*)zw_s)[tid + 128] = zw[rp * 128 + tid + 128];
        __syncthreads();
        int t = tid & 63, rs = tid >> 6;
        float acc = lb_s[t];
        #pragma unroll
        for (int k = 0; k < 128; k += 4) {
            float4 w = *((const float4*)&lw_s[t * 132 + k]);
            float4 z = *((const float4*)&zw_s[rs][k]);
            acc += w.x * z.x + w.y * z.y + w.z * z.z + w.w * z.w;
        }
        float zt = fmaxf(acc, 0.0f);
        zt_s[rs][t] = zt;
        g_zt[(row0 + rp + rs) * 64 + t] = zt;
        __syncthreads();
        if (tid < 64) {
            int r = tid >> 5, j = tid & 31;
            float h = ab_s[j];
            #pragma unroll
            for (int k = 0; k < 64; k++) h += zt_s[r][k] * awT[k * 32 + j];
            h = tanhf(h);
            float v = h * a2_s[j];
            #pragma unroll
            for (int o = 16; o; o >>= 1) v += __shfl_xor_sync(0xffffffffu, v, o);
            if (j == 0) g_s[row0 + rp + r] = v + a2b_s;
        }
        __syncthreads();
    }
}

// ---------------- K2: per-group m, e, T ----------------
__global__ void __launch_bounds__(1024) k_stats() {
    __shared__ float red[1024];
    int g = blockIdx.x;
    int base = g * B_HALF;
    int tid = threadIdx.x;
    float m = fmaxf(g_s[base + tid], g_s[base + tid + 1024]);
    red[tid] = m; __syncthreads();
    for (int s = 512; s > 0; s >>= 1) {
        if (tid < s) red[tid] = fmaxf(red[tid], red[tid + s]);
        __syncthreads();
    }
    m = red[0];
    __syncthreads();
    float e0 = __expf(g_s[base + tid] - m);
    float e1 = __expf(g_s[base + tid + 1024] - m);
    g_e[base + tid] = e0; g_e[base + tid + 1024] = e1;
    red[tid] = e0 + e1; __syncthreads();
    for (int s = 512; s > 0; s >>= 1) {
        if (tid < s) red[tid] += red[tid + s];
        __syncthreads();
    }
    if (tid == 0) g_T[g] = red[0];
}

// ---------------- K2b: partial Z over 128-row chunks ----------------
__global__ void __launch_bounds__(256) k_zpart() {
    __shared__ float red[256];
    int b = blockIdx.x;
    int base = b * 128;
    int d = threadIdx.x & 63, sub = threadIdx.x >> 6;
    float z = 0.f;
    #pragma unroll 4
    for (int r = sub; r < 128; r += 4)
        z += g_e[base + r] * g_zt[(base + r) * 64 + d];
    red[threadIdx.x] = z;
    __syncthreads();
    if (sub == 0)
        g_Zp[b * 64 + d] = red[d] + red[64 + d] + red[128 + d] + red[192 + d];
}

// ---------------- K3: pred[row] = pooled@Ww.T + Wwb + c@Wk.T + Wkb --------
__global__ void __launch_bounds__(128) k_pred(
    const float* __restrict__ c,
    const float* __restrict__ Wkw, const float* __restrict__ Wkb,
    const float* __restrict__ Ww0w, const float* __restrict__ Ww0b,
    const float* __restrict__ Ww1w, const float* __restrict__ Ww1b)
{
    extern __shared__ float sm3[];
    float* W_s = sm3;
    float* u_s = sm3 + 128 * 132;
    float* b_s = u_s + 128;
    float* Zs  = b_s + 128;
    int tid = threadIdx.x;
    int row0 = blockIdx.x * 32;
    int g = (row0 >= B_HALF);
    const float* Ww = g ? Ww1w : Ww0w;
    const float* Wb = g ? Ww1b : Ww0b;
    for (int n = tid; n < 4096; n += 128) {
        int j = n >> 5, q = n & 31;
        float4 v; int off;
        if (q < 16) { v = ((const float4*)Ww)[j * 16 + q];         off = q * 4; }
        else        { v = ((const float4*)Wkw)[j * 16 + (q - 16)]; off = 64 + (q - 16) * 4; }
        *((float4*)&W_s[j * 132 + off]) = v;
    }
    b_s[tid] = Wb[tid] + Wkb[tid];
    if (tid < 64) {
        float z = 0.f;
        #pragma unroll
        for (int p = 0; p < 16; p++) z += g_Zp[(g * 16 + p) * 64 + tid];
        Zs[tid] = z;
    }
    __syncthreads();
    float Tg = g_T[g];
    for (int r = 0; r < 32; r++) {
        int row = row0 + r;
        if (tid < 64) {
            float e  = g_e[row];
            float zt = g_zt[row * 64 + tid];
            u_s[tid] = (Zs[tid] - e * zt) / (Tg - e);
        } else {
            u_s[tid] = c[row * 64 + (tid - 64)];
        }
        __syncthreads();
        float acc = b_s[tid];
        #pragma unroll
        for (int k = 0; k < 128; k += 4) {
            float4 w = *((const float4*)&W_s[tid * 132 + k]);
            float4 u = *((const float4*)&u_s[k]);
            acc += w.x * u.x + w.y * u.y + w.z * u.z + w.w * u.w;
        }
        g_pred[row * 128 + tid] = acc;
        __syncthreads();
    }
}

// ---------------- K3b: bf16 split into A'/B' (K'=384) --------------------
// 131072 float4 elements total -> 512 blocks x 256 threads.
__global__ void __launch_bounds__(256) k_cvt(
    const float* __restrict__ zw0, const float* __restrict__ zw1)
{
    int n = blockIdx.x * 256 + threadIdx.x;
    int row = n >> 5;
    int c4 = (n & 31) << 2;
    const float* src = (row < B_HALF) ? (zw0 + row * 128)
                                      : (zw1 + (row - B_HALF) * 128);
    float4 x = *((const float4*)(src + c4));
    float4 y = *((const float4*)(g_pred + row * 128 + c4));
    float xv[4] = {x.x, x.y, x.z, x.w};
    float yv[4] = {y.x, y.y, y.z, y.w};
    unsigned short ah[4], al[4], bh[4], bl[4];
    #pragma unroll
    for (int i = 0; i < 4; i++) {
        __nv_bfloat16 h = __float2bfloat16(xv[i]);
        __nv_bfloat16 l = __float2bfloat16(xv[i] - __bfloat162float(h));
        ah[i] = __bfloat16_as_ushort(h);
        al[i] = __bfloat16_as_ushort(l);
        h = __float2bfloat16(yv[i]);
        l = __float2bfloat16(yv[i] - __bfloat162float(h));
        bh[i] = __bfloat16_as_ushort(h);
        bl[i] = __bfloat16_as_ushort(l);
    }
    unsigned short* Ad = g_A + row * 384 + c4;
    unsigned short* Bd = g_B + row * 384 + c4;
    *(ushort4*)(Ad)       = make_ushort4(ah[0], ah[1], ah[2], ah[3]);
    *(ushort4*)(Ad + 128) = make_ushort4(al[0], al[1], al[2], al[3]);
    *(ushort4*)(Ad + 256) = make_ushort4(ah[0], ah[1], ah[2], ah[3]);
    *(ushort4*)(Bd)       = make_ushort4(bh[0], bh[1], bh[2], bh[3]);
    *(ushort4*)(Bd + 128) = make_ushort4(bh[0], bh[1], bh[2], bh[3]);
    *(ushort4*)(Bd + 256) = make_ushort4(bl[0], bl[1], bl[2], bl[3]);
}

// ---------------- K4: HMMA bf16 GEMM (K'=384) + fused LSE partials -------
// 128x128 block tile, 8 warps of 64x32, mma.m16n8k16, cp.async double buffer.
#define KC 64
#define NCHUNK 6
#define ROWB 144            // padded smem row bytes (72 bf16): 4-bank shift
#define ABUF 18432          // 128 * 144
#define SM_A0 0
#define SM_B0 36864
#define SM_RED 73728
#define GSMEM (73728 + 4096)

__global__ void __launch_bounds__(256) k_gemm_mma() {
    extern __shared__ __align__(128) char smem[];
    uint32_t sb = smem_u32(smem);
    int tid = threadIdx.x, wid = tid >> 5, lane = tid & 31;
    int cb = blockIdx.x, rb = blockIdx.y;
    int wr = wid >> 2, wc = wid & 3;      // warp tile: rows wr*64, cols wc*32
    const unsigned short* asrc = g_A + (size_t)rb * 128 * 384;
    const unsigned short* bsrc = g_B + (size_t)cb * 128 * 384;

    float acc[4][4][4];
    #pragma unroll
    for (int i = 0; i < 4; i++)
        #pragma unroll
        for (int j = 0; j < 4; j++)
            #pragma unroll
            for (int q = 0; q < 4; q++) acc[i][j][q] = 0.f;

    // cp.async prefetch of one K-chunk (A + B) into buffer `buf`
    #define PREFETCH(c, buf) do {                                              \
        const unsigned short* _ap = asrc + (c) * KC;                           \
        const unsigned short* _bp = bsrc + (c) * KC;                           \
        _Pragma("unroll")                                                      \
        for (int _i = 0; _i < 4; _i++) {                                       \
            int _idx = tid + _i * 256;                                         \
            int _row = _idx >> 3, _kc = _idx & 7;                              \
            uint32_t _da = sb + SM_A0 + (buf) * ABUF + _row * ROWB + _kc * 16; \
            asm volatile("cp.async.cg.shared.global [%0], [%1], 16;"           \
                :: "r"(_da), "l"(_ap + _row * 384 + _kc * 8));                 \
            uint32_t _db = sb + SM_B0 + (buf) * ABUF + _row * ROWB + _kc * 16; \
            asm volatile("cp.async.cg.shared.global [%0], [%1], 16;"           \
                :: "r"(_db), "l"(_bp + _row * 384 + _kc * 8));                 \
        }                                                                      \
        asm volatile("cp.async.commit_group;");                                \
    } while (0)

    int arow = lane & 15, ahalf = lane >> 4;
    int brow = lane & 7,  bhalf = (lane >> 3) & 1;

    PREFETCH(0, 0);
    for (int c = 0; c < NCHUNK; c++) {
        int buf = c & 1;
        if (c + 1 < NCHUNK) {
            PREFETCH(c + 1, buf ^ 1);
            asm volatile("cp.async.wait_group 1;");
        } else {
            asm volatile("cp.async.wait_group 0;");
        }
        __syncthreads();
        uint32_t abase = sb + SM_A0 + buf * ABUF;
        uint32_t bbase = sb + SM_B0 + buf * ABUF;
        #pragma unroll
        for (int k0 = 0; k0 < KC; k0 += 16) {
            uint32_t a[4][4], b[4][2];
            #pragma unroll
            for (int mi = 0; mi < 4; mi++) {
                uint32_t ad = abase + (wr * 64 + mi * 16 + arow) * ROWB
                            + (k0 + 8 * ahalf) * 2;
                asm volatile("ldmatrix.sync.aligned.m8n8.x4.shared.b16 "
                             "{%0,%1,%2,%3}, [%4];"
                    : "=r"(a[mi][0]), "=r"(a[mi][1]),
                      "=r"(a[mi][2]), "=r"(a[mi][3]) : "r"(ad));
            }
            #pragma unroll
            for (int nj = 0; nj < 4; nj++) {
                uint32_t bd = bbase + (wc * 32 + nj * 8 + brow) * ROWB
                            + (k0 + 8 * bhalf) * 2;
                asm volatile("ldmatrix.sync.aligned.m8n8.x2.shared.b16 "
                             "{%0,%1}, [%2];"
                    : "=r"(b[nj][0]), "=r"(b[nj][1]) : "r"(bd));
            }
            #pragma unroll
            for (int mi = 0; mi < 4; mi++)
                #pragma unroll
                for (int nj = 0; nj < 4; nj++)
                    asm volatile(
                        "mma.sync.aligned.m16n8k16.row.col.f32.bf16.bf16.f32 "
                        "{%0,%1,%2,%3}, {%4,%5,%6,%7}, {%8,%9}, {%0,%1,%2,%3};"
                        : "+f"(acc[mi][nj][0]), "+f"(acc[mi][nj][1]),
                          "+f"(acc[mi][nj][2]), "+f"(acc[mi][nj][3])
                        : "r"(a[mi][0]), "r"(a[mi][1]),
                          "r"(a[mi][2]), "r"(a[mi][3]),
                          "r"(b[nj][0]), "r"(b[nj][1]));
        }
        __syncthreads();
    }

    // ---- fused epilogue: per-row max / sum-exp, diag capture ----
    float* pMs = (float*)(smem + SM_RED);   // [128][4]
    float* pSs = pMs + 512;
    int r4 = lane >> 2;
    #pragma unroll
    for (int mi = 0; mi < 4; mi++) {
        #pragma unroll
        for (int half = 0; half < 2; half++) {
            float m = -1e30f;
            #pragma unroll
            for (int nj = 0; nj < 4; nj++) {
                m = fmaxf(m, acc[mi][nj][half * 2]);
                m = fmaxf(m, acc[mi][nj][half * 2 + 1]);
            }
            m = fmaxf(m, __shfl_xor_sync(0xffffffffu, m, 1));
            m = fmaxf(m, __shfl_xor_sync(0xffffffffu, m, 2));
            float s = 0.f;
            #pragma unroll
            for (int nj = 0; nj < 4; nj++)
                s += __expf(acc[mi][nj][half * 2] - m)
                   + __expf(acc[mi][nj][half * 2 + 1] - m);
            s += __shfl_xor_sync(0xffffffffu, s, 1);
            s += __shfl_xor_sync(0xffffffffu, s, 2);
            if ((lane & 3) == 0) {
                int lr = wr * 64 + mi * 16 + half * 8 + r4;
                pMs[lr * 4 + wc] = m;
                pSs[lr * 4 + wc] = s;
            }
        }
    }
    if (rb == cb) {
        int c2 = (lane & 3) * 2;
        #pragma unroll
        for (int mi = 0; mi < 4; mi++)
            #pragma unroll
            for (int nj = 0; nj < 4; nj++)
                #pragma unroll
                for (int q = 0; q < 4; q++) {
                    int lr = wr * 64 + mi * 16 + (q >> 1) * 8 + r4;
                    int lc = wc * 32 + nj * 8 + c2 + (q & 1);
                    if (lr == lc) g_diag[rb * 128 + lr] = acc[mi][nj][q];
                }
    }
    __syncthreads();
    if (tid < 128) {
        float M = fmaxf(fmaxf(pMs[tid * 4], pMs[tid * 4 + 1]),
                        fmaxf(pMs[tid * 4 + 2], pMs[tid * 4 + 3]));
        float S = 0.f;
        #pragma unroll
        for (int w = 0; w < 4; w++)
            S += pSs[tid * 4 + w] * __expf(pMs[tid * 4 + w] - M);
        int grow = rb * 128 + tid;
        g_pM[cb * B_TOT + grow] = M;
        g_pS[cb * B_TOT + grow] = S;
    }
}

// ---------------- K5: combine 32 partials per row -> lse - diag ----------
__global__ void __launch_bounds__(128) k_combine() {
    int i = blockIdx.x * 128 + threadIdx.x;
    float M = -1e30f;
    #pragma unroll
    for (int p = 0; p < 32; p++) M = fmaxf(M, g_pM[p * B_TOT + i]);
    float S = 0.f;
    #pragma unroll
    for (int p = 0; p < 32; p++)
        S += g_pS[p * B_TOT + i] * __expf(g_pM[p * B_TOT + i] - M);
    g_rowvals[i] = M + logf(S) - g_diag[i];
}

// ---------------- K6: deterministic final reduction ----------------------
__global__ void __launch_bounds__(1024) k_final(float* __restrict__ out) {
    __shared__ double red[1024];
    int tid = threadIdx.x;
    double v = (double)g_rowvals[tid] + (double)g_rowvals[tid + 1024]
             + (double)g_rowvals[tid + 2048] + (double)g_rowvals[tid + 3072];
    red[tid] = v; __syncthreads();
    for (int s = 512; s > 0; s >>= 1) {
        if (tid < s) red[tid] += red[tid + s];
        __syncthreads();
    }
    if (tid == 0) out[0] = (float)(red[0] / 4096.0);
}

extern "C" void kernel_launch(void* const* d_in, const int* in_sizes, int n_in,
                              void* d_out, int out_size) {
    const float* zw0  = (const float*)d_in[0];
    const float* zw1  = (const float*)d_in[1];
    const float* c    = (const float*)d_in[2];
    const float* Wkw  = (const float*)d_in[3];
    const float* Wkb  = (const float*)d_in[4];
    const float* Ww0w = (const float*)d_in[5];
    const float* Ww0b = (const float*)d_in[6];
    const float* Ww1w = (const float*)d_in[7];
    const float* Ww1b = (const float*)d_in[8];
    const float* l0w  = (const float*)d_in[9];
    const float* l0b  = (const float*)d_in[10];
    const float* l1w  = (const float*)d_in[11];
    const float* l1b  = (const float*)d_in[12];
    const float* a01w = (const float*)d_in[13];
    const float* a01b = (const float*)d_in[14];
    const float* a02w = (const float*)d_in[15];
    const float* a02b = (const float*)d_in[16];
    const float* a11w = (const float*)d_in[17];
    const float* a11b = (const float*)d_in[18];
    const float* a12w = (const float*)d_in[19];
    const float* a12b = (const float*)d_in[20];
    float* out = (float*)d_out;

    cudaFuncSetAttribute(k_pred, cudaFuncAttributeMaxDynamicSharedMemorySize,
                         (128 * 132 + 128 + 128 + 64) * 4);
    cudaFuncSetAttribute(k_gemm_mma, cudaFuncAttributeMaxDynamicSharedMemorySize,
                         GSMEM);

    k_zt_s<<<128, 128>>>(zw0, zw1, l0w, l0b, l1w, l1b,
                         a01w, a01b, a02w, a02b, a11w, a11b, a12w, a12b);
    k_stats<<<2, 1024>>>();
    k_zpart<<<32, 256>>>();
    k_pred<<<128, 128, (128 * 132 + 128 + 128 + 64) * 4>>>(c, Wkw, Wkb,
                                                           Ww0w, Ww0b, Ww1w, Ww1b);
    k_cvt<<<512, 256>>>(zw0, zw1);
    k_gemm_mma<<<dim3(32, 32), 256, GSMEM>>>();
    k_combine<<<32, 128>>>();
    k_final<<<1, 1024>>>(out);
}

// round 7
// speedup vs baseline: 2.0749x; 1.1191x over previous
#include <cuda_runtime.h>
#include <cuda_bf16.h>
#include <cstdint>

#define B_TOT 4096
#define B_HALF 2048
#define PAD 130

// ---------------- device scratch ----------------
__device__ float g_zt[B_TOT * 64];
__device__ float g_s[B_TOT];
__device__ float g_e[B_TOT];
__device__ float g_T[2];
__device__ float g_Zp[32 * 64];
__device__ float g_Z[128];
__device__ __align__(16) float g_u[B_TOT * 128];
__device__ __align__(16) float g_pred[B_TOT * 128];
__device__ float g_diag[B_TOT];
__device__ float g_pM[32 * B_TOT];
__device__ float g_pS[32 * B_TOT];
__device__ float g_rowvals[B_TOT];
__device__ __align__(16) unsigned short g_A[B_TOT * 384];  // bf16 [hi|lo|hi]
__device__ __align__(16) unsigned short g_B[B_TOT * 384];  // bf16 [hi|hi|lo]

__device__ __forceinline__ uint32_t smem_u32(const void* p) {
    uint32_t a;
    asm("{ .reg .u64 t; cvta.to.shared.u64 t, %1; cvt.u32.u64 %0, t; }"
        : "=r"(a) : "l"(p));
    return a;
}
__device__ __forceinline__ void ffma2(unsigned long long& d,
                                      unsigned long long a,
                                      unsigned long long b) {
    asm("fma.rn.f32x2 %0, %1, %2, %0;" : "+l"(d) : "l"(a), "l"(b));
}

// ---------------- K1: zt = relu(zw @ lw.T + lb); attention score s --------
// 512 blocks x 8 rows.
__global__ void __launch_bounds__(128) k_zt_s(
    const float* __restrict__ zw0, const float* __restrict__ zw1,
    const float* __restrict__ l0w, const float* __restrict__ l0b,
    const float* __restrict__ l1w, const float* __restrict__ l1b,
    const float* __restrict__ a01w, const float* __restrict__ a01b,
    const float* __restrict__ a02w, const float* __restrict__ a02b,
    const float* __restrict__ a11w, const float* __restrict__ a11b,
    const float* __restrict__ a12w, const float* __restrict__ a12b)
{
    __shared__ float lw_s[64 * 132];
    __shared__ float awT[64 * 32];
    __shared__ float lb_s[64], ab_s[32], a2_s[32];
    __shared__ float zw_s[2][128];
    __shared__ float zt_s[2][64];
    __shared__ float a2b_s;
    int tid = threadIdx.x;
    int row0 = blockIdx.x * 8;
    int g = (row0 >= B_HALF);
    const float* zw  = g ? (zw1 + (row0 - B_HALF) * 128) : (zw0 + row0 * 128);
    const float* lw  = g ? l1w : l0w;
    const float* lb  = g ? l1b : l0b;
    const float* a1w = g ? a11w : a01w;
    const float* a1b = g ? a11b : a01b;
    const float* a2w = g ? a12w : a02w;
    const float* a2b = g ? a12b : a02b;

    for (int n = tid; n < 2048; n += 128) {
        float4 v = ((const float4*)lw)[n];
        int t = n >> 5; int k4 = (n & 31) * 4;
        *((float4*)&lw_s[t * 132 + k4]) = v;
    }
    for (int n = tid; n < 512; n += 128) {
        float4 v = ((const float4*)a1w)[n];
        int t = n >> 4; int k = (n & 15) * 4;
        awT[(k + 0) * 32 + t] = v.x; awT[(k + 1) * 32 + t] = v.y;
        awT[(k + 2) * 32 + t] = v.z; awT[(k + 3) * 32 + t] = v.w;
    }
    if (tid < 64) lb_s[tid] = lb[tid];
    if (tid < 32) { ab_s[tid] = a1b[tid]; a2_s[tid] = a2w[tid]; }
    if (tid == 0) a2b_s = a2b[0];
    __syncthreads();

    for (int rp = 0; rp < 8; rp += 2) {
        ((float*)zw_s)[tid]       = zw[rp * 128 + tid];
        ((float*)zw_s)[tid + 128] = zw[rp * 128 + tid + 128];
        __syncthreads();
        int t = tid & 63, rs = tid >> 6;
        float acc = lb_s[t];
        #pragma unroll
        for (int k = 0; k < 128; k += 4) {
            float4 w = *((const float4*)&lw_s[t * 132 + k]);
            float4 z = *((const float4*)&zw_s[rs][k]);
            acc += w.x * z.x + w.y * z.y + w.z * z.z + w.w * z.w;
        }
        float zt = fmaxf(acc, 0.0f);
        zt_s[rs][t] = zt;
        g_zt[(row0 + rp + rs) * 64 + t] = zt;
        __syncthreads();
        if (tid < 64) {
            int r = tid >> 5, j = tid & 31;
            float h = ab_s[j];
            #pragma unroll
            for (int k = 0; k < 64; k++) h += zt_s[r][k] * awT[k * 32 + j];
            h = tanhf(h);
            float v = h * a2_s[j];
            #pragma unroll
            for (int o = 16; o; o >>= 1) v += __shfl_xor_sync(0xffffffffu, v, o);
            if (j == 0) g_s[row0 + rp + r] = v + a2b_s;
        }
        __syncthreads();
    }
}

// ---------------- K2: per-group m, e, T ----------------
__global__ void __launch_bounds__(1024) k_stats() {
    __shared__ float red[1024];
    int g = blockIdx.x;
    int base = g * B_HALF;
    int tid = threadIdx.x;
    float m = fmaxf(g_s[base + tid], g_s[base + tid + 1024]);
    red[tid] = m; __syncthreads();
    for (int s = 512; s > 0; s >>= 1) {
        if (tid < s) red[tid] = fmaxf(red[tid], red[tid + s]);
        __syncthreads();
    }
    m = red[0];
    __syncthreads();
    float e0 = __expf(g_s[base + tid] - m);
    float e1 = __expf(g_s[base + tid + 1024] - m);
    g_e[base + tid] = e0; g_e[base + tid + 1024] = e1;
    red[tid] = e0 + e1; __syncthreads();
    for (int s = 512; s > 0; s >>= 1) {
        if (tid < s) red[tid] += red[tid + s];
        __syncthreads();
    }
    if (tid == 0) g_T[g] = red[0];
}

// ---------------- K2b: partial Z over 128-row chunks ----------------
__global__ void __launch_bounds__(256) k_zpart() {
    __shared__ float red[256];
    int b = blockIdx.x;
    int base = b * 128;
    int d = threadIdx.x & 63, sub = threadIdx.x >> 6;
    float z = 0.f;
    #pragma unroll 4
    for (int r = sub; r < 128; r += 4)
        z += g_e[base + r] * g_zt[(base + r) * 64 + d];
    red[threadIdx.x] = z;
    __syncthreads();
    if (sub == 0)
        g_Zp[b * 64 + d] = red[d] + red[64 + d] + red[128 + d] + red[192 + d];
}

// ---------------- K2c: fold Z partials ----------------
__global__ void __launch_bounds__(128) k_zfold() {
    int tid = threadIdx.x;          // tid = g*64 + d
    int g = tid >> 6, d = tid & 63;
    float z = 0.f;
    #pragma unroll
    for (int p = 0; p < 16; p++) z += g_Zp[(g * 16 + p) * 64 + d];
    g_Z[tid] = z;
}

// ---------------- K3a: build u = [pooled | c]  (4096 x 128) --------------
__global__ void __launch_bounds__(256) k_build_u(const float* __restrict__ c) {
    int idx = blockIdx.x * 256 + threadIdx.x;    // 524288 total
    int row = idx >> 7, col = idx & 127;
    int g = (row >= B_HALF);
    float v;
    if (col < 64) {
        float e  = g_e[row];
        float zt = g_zt[row * 64 + col];
        v = (g_Z[g * 64 + col] - e * zt) / (g_T[g] - e);
    } else {
        v = c[row * 64 + (col - 64)];
    }
    g_u[row * 128 + col] = v;
}

// ---------------- K3b: pred = u @ W'^T + bias  (FFMA2 tiles) --------------
// 32 blocks x 256 threads; 128x128 output tile, K=128.
__global__ void __launch_bounds__(256) k_pred_gemm(
    const float* __restrict__ Wkw, const float* __restrict__ Wkb,
    const float* __restrict__ Ww0w, const float* __restrict__ Ww0b,
    const float* __restrict__ Ww1w, const float* __restrict__ Ww1b)
{
    extern __shared__ float sm[];
    float* As   = sm;                    // [128][130]
    float* Bs   = sm + 128 * PAD;        // [128][130]
    float* bias = sm + 2 * 128 * PAD;    // [128]
    int tid = threadIdx.x;
    int row0 = blockIdx.x * 128;
    int g = (row0 >= B_HALF);
    const float* Ww = g ? Ww1w : Ww0w;
    const float* Wb = g ? Ww1b : Ww0b;

    const float4* usrc = (const float4*)(g_u + row0 * 128);
    for (int n = tid; n < 4096; n += 256) {
        int r = n >> 5, c4 = (n & 31) * 4;
        float4 v = usrc[n];
        *(float2*)&As[r * PAD + c4]     = make_float2(v.x, v.y);
        *(float2*)&As[r * PAD + c4 + 2] = make_float2(v.z, v.w);
        int j = n >> 5, q = n & 31;
        float4 w; int off;
        if (q < 16) { w = ((const float4*)Ww)[j * 16 + q];         off = q * 4; }
        else        { w = ((const float4*)Wkw)[j * 16 + (q - 16)]; off = 64 + (q - 16) * 4; }
        *(float2*)&Bs[j * PAD + off]     = make_float2(w.x, w.y);
        *(float2*)&Bs[j * PAD + off + 2] = make_float2(w.z, w.w);
    }
    if (tid < 128) bias[tid] = Wb[tid] + Wkb[tid];
    __syncthreads();

    int tx = tid & 15, ty = tid >> 4;
    unsigned long long acc2[8][8];
    #pragma unroll
    for (int i = 0; i < 8; i++)
        #pragma unroll
        for (int j = 0; j < 8; j++) acc2[i][j] = 0ull;
    const float* arow = As + ty * PAD;
    const float* brow = Bs + tx * PAD;
    #pragma unroll 2
    for (int k = 0; k < 128; k += 2) {
        unsigned long long a[8], b[8];
        #pragma unroll
        for (int i = 0; i < 8; i++)
            a[i] = *((const unsigned long long*)&arow[i * 16 * PAD + k]);
        #pragma unroll
        for (int j = 0; j < 8; j++)
            b[j] = *((const unsigned long long*)&brow[j * 16 * PAD + k]);
        #pragma unroll
        for (int i = 0; i < 8; i++)
            #pragma unroll
            for (int j = 0; j < 8; j++)
                ffma2(acc2[i][j], a[i], b[j]);
    }
    #pragma unroll
    for (int i = 0; i < 8; i++) {
        int row = row0 + ty + 16 * i;
        #pragma unroll
        for (int j = 0; j < 8; j++) {
            int col = tx + 16 * j;
            unsigned long long u = acc2[i][j];
            float lo = __uint_as_float((unsigned)u);
            float hi = __uint_as_float((unsigned)(u >> 32));
            g_pred[row * 128 + col] = lo + hi + bias[col];
        }
    }
}

// ---------------- K3c: bf16 split into A'/B' (K'=384) --------------------
__global__ void __launch_bounds__(256) k_cvt(
    const float* __restrict__ zw0, const float* __restrict__ zw1)
{
    int n = blockIdx.x * 256 + threadIdx.x;
    int row = n >> 5;
    int c4 = (n & 31) << 2;
    const float* src = (row < B_HALF) ? (zw0 + row * 128)
                                      : (zw1 + (row - B_HALF) * 128);
    float4 x = *((const float4*)(src + c4));
    float4 y = *((const float4*)(g_pred + row * 128 + c4));
    float xv[4] = {x.x, x.y, x.z, x.w};
    float yv[4] = {y.x, y.y, y.z, y.w};
    unsigned short ah[4], al[4], bh[4], bl[4];
    #pragma unroll
    for (int i = 0; i < 4; i++) {
        __nv_bfloat16 h = __float2bfloat16(xv[i]);
        __nv_bfloat16 l = __float2bfloat16(xv[i] - __bfloat162float(h));
        ah[i] = __bfloat16_as_ushort(h);
        al[i] = __bfloat16_as_ushort(l);
        h = __float2bfloat16(yv[i]);
        l = __float2bfloat16(yv[i] - __bfloat162float(h));
        bh[i] = __bfloat16_as_ushort(h);
        bl[i] = __bfloat16_as_ushort(l);
    }
    unsigned short* Ad = g_A + row * 384 + c4;
    unsigned short* Bd = g_B + row * 384 + c4;
    *(ushort4*)(Ad)       = make_ushort4(ah[0], ah[1], ah[2], ah[3]);
    *(ushort4*)(Ad + 128) = make_ushort4(al[0], al[1], al[2], al[3]);
    *(ushort4*)(Ad + 256) = make_ushort4(ah[0], ah[1], ah[2], ah[3]);
    *(ushort4*)(Bd)       = make_ushort4(bh[0], bh[1], bh[2], bh[3]);
    *(ushort4*)(Bd + 128) = make_ushort4(bh[0], bh[1], bh[2], bh[3]);
    *(ushort4*)(Bd + 256) = make_ushort4(bl[0], bl[1], bl[2], bl[3]);
}

// ---------------- K4: HMMA bf16 GEMM (K'=384) + fused LSE partials -------
#define KC 64
#define NCHUNK 6
#define ROWB 144
#define ABUF 18432
#define SM_A0 0
#define SM_B0 36864
#define SM_RED 73728
#define GSMEM (73728 + 4096)

__global__ void __launch_bounds__(256) k_gemm_mma() {
    extern __shared__ __align__(128) char smem[];
    uint32_t sb = smem_u32(smem);
    int tid = threadIdx.x, wid = tid >> 5, lane = tid & 31;
    int cb = blockIdx.x, rb = blockIdx.y;
    int wr = wid >> 2, wc = wid & 3;
    const unsigned short* asrc = g_A + (size_t)rb * 128 * 384;
    const unsigned short* bsrc = g_B + (size_t)cb * 128 * 384;

    float acc[4][4][4];
    #pragma unroll
    for (int i = 0; i < 4; i++)
        #pragma unroll
        for (int j = 0; j < 4; j++)
            #pragma unroll
            for (int q = 0; q < 4; q++) acc[i][j][q] = 0.f;

    #define PREFETCH(c, buf) do {                                              \
        const unsigned short* _ap = asrc + (c) * KC;                           \
        const unsigned short* _bp = bsrc + (c) * KC;                           \
        _Pragma("unroll")                                                      \
        for (int _i = 0; _i < 4; _i++) {                                       \
            int _idx = tid + _i * 256;                                         \
            int _row = _idx >> 3, _kc = _idx & 7;                              \
            uint32_t _da = sb + SM_A0 + (buf) * ABUF + _row * ROWB + _kc * 16; \
            asm volatile("cp.async.cg.shared.global [%0], [%1], 16;"           \
                :: "r"(_da), "l"(_ap + _row * 384 + _kc * 8));                 \
            uint32_t _db = sb + SM_B0 + (buf) * ABUF + _row * ROWB + _kc * 16; \
            asm volatile("cp.async.cg.shared.global [%0], [%1], 16;"           \
                :: "r"(_db), "l"(_bp + _row * 384 + _kc * 8));                 \
        }                                                                      \
        asm volatile("cp.async.commit_group;");                                \
    } while (0)

    int arow = lane & 15, ahalf = lane >> 4;
    int brow = lane & 7,  bhalf = (lane >> 3) & 1;

    PREFETCH(0, 0);
    for (int c = 0; c < NCHUNK; c++) {
        int buf = c & 1;
        if (c + 1 < NCHUNK) {
            PREFETCH(c + 1, buf ^ 1);
            asm volatile("cp.async.wait_group 1;");
        } else {
            asm volatile("cp.async.wait_group 0;");
        }
        __syncthreads();
        uint32_t abase = sb + SM_A0 + buf * ABUF;
        uint32_t bbase = sb + SM_B0 + buf * ABUF;
        #pragma unroll
        for (int k0 = 0; k0 < KC; k0 += 16) {
            uint32_t a[4][4], b[4][2];
            #pragma unroll
            for (int mi = 0; mi < 4; mi++) {
                uint32_t ad = abase + (wr * 64 + mi * 16 + arow) * ROWB
                            + (k0 + 8 * ahalf) * 2;
                asm volatile("ldmatrix.sync.aligned.m8n8.x4.shared.b16 "
                             "{%0,%1,%2,%3}, [%4];"
                    : "=r"(a[mi][0]), "=r"(a[mi][1]),
                      "=r"(a[mi][2]), "=r"(a[mi][3]) : "r"(ad));
            }
            #pragma unroll
            for (int nj = 0; nj < 4; nj++) {
                uint32_t bd = bbase + (wc * 32 + nj * 8 + brow) * ROWB
                            + (k0 + 8 * bhalf) * 2;
                asm volatile("ldmatrix.sync.aligned.m8n8.x2.shared.b16 "
                             "{%0,%1}, [%2];"
                    : "=r"(b[nj][0]), "=r"(b[nj][1]) : "r"(bd));
            }
            #pragma unroll
            for (int mi = 0; mi < 4; mi++)
                #pragma unroll
                for (int nj = 0; nj < 4; nj++)
                    asm volatile(
                        "mma.sync.aligned.m16n8k16.row.col.f32.bf16.bf16.f32 "
                        "{%0,%1,%2,%3}, {%4,%5,%6,%7}, {%8,%9}, {%0,%1,%2,%3};"
                        : "+f"(acc[mi][nj][0]), "+f"(acc[mi][nj][1]),
                          "+f"(acc[mi][nj][2]), "+f"(acc[mi][nj][3])
                        : "r"(a[mi][0]), "r"(a[mi][1]),
                          "r"(a[mi][2]), "r"(a[mi][3]),
                          "r"(b[nj][0]), "r"(b[nj][1]));
        }
        __syncthreads();
    }

    float* pMs = (float*)(smem + SM_RED);
    float* pSs = pMs + 512;
    int r4 = lane >> 2;
    #pragma unroll
    for (int mi = 0; mi < 4; mi++) {
        #pragma unroll
        for (int half = 0; half < 2; half++) {
            float m = -1e30f;
            #pragma unroll
            for (int nj = 0; nj < 4; nj++) {
                m = fmaxf(m, acc[mi][nj][half * 2]);
                m = fmaxf(m, acc[mi][nj][half * 2 + 1]);
            }
            m = fmaxf(m, __shfl_xor_sync(0xffffffffu, m, 1));
            m = fmaxf(m, __shfl_xor_sync(0xffffffffu, m, 2));
            float s = 0.f;
            #pragma unroll
            for (int nj = 0; nj < 4; nj++)
                s += __expf(acc[mi][nj][half * 2] - m)
                   + __expf(acc[mi][nj][half * 2 + 1] - m);
            s += __shfl_xor_sync(0xffffffffu, s, 1);
            s += __shfl_xor_sync(0xffffffffu, s, 2);
            if ((lane & 3) == 0) {
                int lr = wr * 64 + mi * 16 + half * 8 + r4;
                pMs[lr * 4 + wc] = m;
                pSs[lr * 4 + wc] = s;
            }
        }
    }
    if (rb == cb) {
        int c2 = (lane & 3) * 2;
        #pragma unroll
        for (int mi = 0; mi < 4; mi++)
            #pragma unroll
            for (int nj = 0; nj < 4; nj++)
                #pragma unroll
                for (int q = 0; q < 4; q++) {
                    int lr = wr * 64 + mi * 16 + (q >> 1) * 8 + r4;
                    int lc = wc * 32 + nj * 8 + c2 + (q & 1);
                    if (lr == lc) g_diag[rb * 128 + lr] = acc[mi][nj][q];
                }
    }
    __syncthreads();
    if (tid < 128) {
        float M = fmaxf(fmaxf(pMs[tid * 4], pMs[tid * 4 + 1]),
                        fmaxf(pMs[tid * 4 + 2], pMs[tid * 4 + 3]));
        float S = 0.f;
        #pragma unroll
        for (int w = 0; w < 4; w++)
            S += pSs[tid * 4 + w] * __expf(pMs[tid * 4 + w] - M);
        int grow = rb * 128 + tid;
        g_pM[cb * B_TOT + grow] = M;
        g_pS[cb * B_TOT + grow] = S;
    }
}

// ---------------- K5: combine 32 partials per row -> lse - diag ----------
__global__ void __launch_bounds__(128) k_combine() {
    int i = blockIdx.x * 128 + threadIdx.x;
    float M = -1e30f;
    #pragma unroll
    for (int p = 0; p < 32; p++) M = fmaxf(M, g_pM[p * B_TOT + i]);
    float S = 0.f;
    #pragma unroll
    for (int p = 0; p < 32; p++)
        S += g_pS[p * B_TOT + i] * __expf(g_pM[p * B_TOT + i] - M);
    g_rowvals[i] = M + logf(S) - g_diag[i];
}

// ---------------- K6: deterministic final reduction ----------------------
__global__ void __launch_bounds__(1024) k_final(float* __restrict__ out) {
    __shared__ double red[1024];
    int tid = threadIdx.x;
    double v = (double)g_rowvals[tid] + (double)g_rowvals[tid + 1024]
             + (double)g_rowvals[tid + 2048] + (double)g_rowvals[tid + 3072];
    red[tid] = v; __syncthreads();
    for (int s = 512; s > 0; s >>= 1) {
        if (tid < s) red[tid] += red[tid + s];
        __syncthreads();
    }
    if (tid == 0) out[0] = (float)(red[0] / 4096.0);
}

extern "C" void kernel_launch(void* const* d_in, const int* in_sizes, int n_in,
                              void* d_out, int out_size) {
    const float* zw0  = (const float*)d_in[0];
    const float* zw1  = (const float*)d_in[1];
    const float* c    = (const float*)d_in[2];
    const float* Wkw  = (const float*)d_in[3];
    const float* Wkb  = (const float*)d_in[4];
    const float* Ww0w = (const float*)d_in[5];
    const float* Ww0b = (const float*)d_in[6];
    const float* Ww1w = (const float*)d_in[7];
    const float* Ww1b = (const float*)d_in[8];
    const float* l0w  = (const float*)d_in[9];
    const float* l0b  = (const float*)d_in[10];
    const float* l1w  = (const float*)d_in[11];
    const float* l1b  = (const float*)d_in[12];
    const float* a01w = (const float*)d_in[13];
    const float* a01b = (const float*)d_in[14];
    const float* a02w = (const float*)d_in[15];
    const float* a02b = (const float*)d_in[16];
    const float* a11w = (const float*)d_in[17];
    const float* a11b = (const float*)d_in[18];
    const float* a12w = (const float*)d_in[19];
    const float* a12b = (const float*)d_in[20];
    float* out = (float*)d_out;

    cudaFuncSetAttribute(k_pred_gemm, cudaFuncAttributeMaxDynamicSharedMemorySize,
                         (2 * 128 * PAD + 128) * 4);
    cudaFuncSetAttribute(k_gemm_mma, cudaFuncAttributeMaxDynamicSharedMemorySize,
                         GSMEM);

    k_zt_s<<<512, 128>>>(zw0, zw1, l0w, l0b, l1w, l1b,
                         a01w, a01b, a02w, a02b, a11w, a11b, a12w, a12b);
    k_stats<<<2, 1024>>>();
    k_zpart<<<32, 256>>>();
    k_zfold<<<1, 128>>>();
    k_build_u<<<2048, 256>>>(c);
    k_pred_gemm<<<32, 256, (2 * 128 * PAD + 128) * 4>>>(Wkw, Wkb,
                                                        Ww0w, Ww0b, Ww1w, Ww1b);
    k_cvt<<<512, 256>>>(zw0, zw1);
    k_gemm_mma<<<dim3(32, 32), 256, GSMEM>>>();
    k_combine<<<32, 128>>>();
    k_final<<<1, 1024>>>(out);
}